// round 3
// baseline (speedup 1.0000x reference)
#include <cuda_runtime.h>
#include <cuda_bf16.h>
#include <cstdint>

// ---------------------------------------------------------------------------
// Problem dims
// ---------------------------------------------------------------------------
#define BB 8
#define UU 128
#define TT 256
#define EE 128
#define HH 128
#define NUM_TILES (BB * UU * 2)          // 2048 tiles of 128 t-rows each

// ---------------------------------------------------------------------------
// Device scratch (no allocs allowed)
// ---------------------------------------------------------------------------
__device__ __align__(16) float g_ue_proj[BB * UU * HH];            // ue @ W1u
__device__ __align__(16) float g_te_proj[BB * TT * HH];            // te @ W1t
__device__ __align__(16) float g_gcomb[BB * HH];                   // ge @ W1g + b1
__device__ __align__(16) __nv_bfloat16 g_W2hi[HH * HH];            // W2^T hi [n][k]
__device__ __align__(16) __nv_bfloat16 g_W2lo[HH * HH];            // W2^T lo [n][k]
__device__ int g_tile_ctr;

// ---------------------------------------------------------------------------
// PTX helpers (plain sm_103-safe: ldmatrix + mma.sync only)
// ---------------------------------------------------------------------------
__device__ __forceinline__ uint32_t smem_to_u32(const void* p) {
    uint32_t a;
    asm("{ .reg .u64 t; cvta.to.shared.u64 t, %1; cvt.u32.u64 %0, t; }"
        : "=r"(a) : "l"(p));
    return a;
}

__device__ __forceinline__ void ldmatrix_x4(uint32_t& r0, uint32_t& r1,
                                            uint32_t& r2, uint32_t& r3,
                                            uint32_t addr) {
    asm volatile("ldmatrix.sync.aligned.m8n8.x4.shared.b16 {%0,%1,%2,%3}, [%4];"
                 : "=r"(r0), "=r"(r1), "=r"(r2), "=r"(r3) : "r"(addr));
}
__device__ __forceinline__ void ldmatrix_x2(uint32_t& r0, uint32_t& r1,
                                            uint32_t addr) {
    asm volatile("ldmatrix.sync.aligned.m8n8.x2.shared.b16 {%0,%1}, [%2];"
                 : "=r"(r0), "=r"(r1) : "r"(addr));
}

__device__ __forceinline__ void mma_bf16(float* c, const uint32_t* a,
                                         const uint32_t* b) {
    asm volatile(
        "mma.sync.aligned.m16n8k16.row.col.f32.bf16.bf16.f32 "
        "{%0,%1,%2,%3}, {%4,%5,%6,%7}, {%8,%9}, {%0,%1,%2,%3};"
        : "+f"(c[0]), "+f"(c[1]), "+f"(c[2]), "+f"(c[3])
        : "r"(a[0]), "r"(a[1]), "r"(a[2]), "r"(a[3]), "r"(b[0]), "r"(b[1]));
}

// ---------------------------------------------------------------------------
// Math helpers
// ---------------------------------------------------------------------------
__device__ __forceinline__ float gelu_f(float x) {
    return 0.5f * x * (1.0f + erff(x * 0.70710678118654752f));
}

// pack two fp32 -> bf16x2 (hi word) + residual bf16x2 (lo word)
__device__ __forceinline__ void split2(float a, float b, uint32_t& hi, uint32_t& lo) {
    __nv_bfloat16 ah = __float2bfloat16(a);
    __nv_bfloat16 bh = __float2bfloat16(b);
    float ar = a - __bfloat162float(ah);
    float br = b - __bfloat162float(bh);
    __nv_bfloat16 al = __float2bfloat16(ar);
    __nv_bfloat16 bl = __float2bfloat16(br);
    hi = (uint32_t)__bfloat16_as_ushort(ah) | ((uint32_t)__bfloat16_as_ushort(bh) << 16);
    lo = (uint32_t)__bfloat16_as_ushort(al) | ((uint32_t)__bfloat16_as_ushort(bl) << 16);
}

// ---------------------------------------------------------------------------
// Prep kernel 1: first-layer projections in fp32
// ---------------------------------------------------------------------------
__global__ __launch_bounds__(128) void proj_kernel(
    const float* __restrict__ ue, const float* __restrict__ te,
    const float* __restrict__ ge, const float* __restrict__ W1,
    const float* __restrict__ b1) {
    __shared__ float s_in[32 * EE];
    int bid = blockIdx.x;
    int tid = threadIdx.x;

    const float* src;
    float* dst;
    const float* W;
    int rows;
    bool add_b1 = false;
    if (bid < 32) {
        src = ue + bid * 32 * EE;  dst = g_ue_proj + bid * 32 * HH;
        W = W1;                    rows = 32;
    } else if (bid < 96) {
        int r = bid - 32;
        src = te + r * 32 * EE;    dst = g_te_proj + r * 32 * HH;
        W = W1 + EE * HH;          rows = 32;
    } else {
        src = ge;                  dst = g_gcomb;
        W = W1 + 2 * EE * HH;      rows = BB;  add_b1 = true;
    }

    for (int i = tid; i < rows * EE; i += 128) s_in[i] = src[i];
    __syncthreads();

    float wcol[EE];
#pragma unroll
    for (int e = 0; e < EE; e++) wcol[e] = W[e * HH + tid];
    float bb = add_b1 ? b1[tid] : 0.0f;

    for (int r = 0; r < rows; r++) {
        float acc = bb;
#pragma unroll
        for (int e = 0; e < EE; e++) acc = fmaf(s_in[r * EE + e], wcol[e], acc);
        dst[r * HH + tid] = acc;
    }
}

// ---------------------------------------------------------------------------
// Prep kernel 2: split W2 (hi/lo bf16), transpose to [n=out][k=in] row-major.
// Also resets the tile-steal counter (runs before main kernel every launch).
// ---------------------------------------------------------------------------
__global__ __launch_bounds__(128) void prep_w2_kernel(const float* __restrict__ W2) {
    int n = threadIdx.x;
    if (n == 0) g_tile_ctr = 0;
    for (int k = 0; k < HH; k++) {
        float w = W2[k * HH + n];
        __nv_bfloat16 hi = __float2bfloat16(w);
        float lof = w - __bfloat162float(hi);
        g_W2hi[n * HH + k] = hi;
        g_W2lo[n * HH + k] = __float2bfloat16(lof);
    }
}

// ---------------------------------------------------------------------------
// Main fused kernel (persistent, 8 warps, HMMA):
//   per tile (b,u,thalf): h1 = gelu(uc + te_proj) -> bf16 hi/lo in SMEM
//   -> 3-product bf16 GEMM vs W2^T (accum in registers)
//   -> +b2, gelu, dot W3, +b3 -> out
// ---------------------------------------------------------------------------
// SMEM layout: padded rows (136 bf16 = 272 B) for conflict-free ldmatrix
static constexpr int ST      = 136;                 // row stride in bf16
static constexpr int STB     = ST * 2;              // row stride in bytes (272)
static constexpr int TILE_B  = 128 * STB;           // 34816 bytes per operand tile
static constexpr int OFF_AHI = 0;
static constexpr int OFF_ALO = OFF_AHI + TILE_B;
static constexpr int OFF_BHI = OFF_ALO + TILE_B;
static constexpr int OFF_BLO = OFF_BHI + TILE_B;
static constexpr int OFF_UC  = OFF_BLO + TILE_B;    // 128 floats
static constexpr int OFF_B2S = OFF_UC + 512;        // 128 floats
static constexpr int OFF_W3S = OFF_B2S + 512;       // 128 floats
static constexpr int OFF_PSUM = OFF_W3S + 512;      // 256 floats
static constexpr int OFF_TILE = OFF_PSUM + 1024;    // stolen tile index
static constexpr int SMEM_MAIN = OFF_TILE + 16;

__global__ __launch_bounds__(256, 1) void pairwise_main(
    const float* __restrict__ b2, const float* __restrict__ W3,
    const float* __restrict__ b3, float* __restrict__ out) {
    extern __shared__ char smem[];
    const uint32_t smem_base = smem_to_u32(smem);
    const int tid  = threadIdx.x;
    const int wid  = tid >> 5;
    const int lane = tid & 31;

    float* uc   = (float*)(smem + OFF_UC);
    float* b2s  = (float*)(smem + OFF_B2S);
    float* w3s  = (float*)(smem + OFF_W3S);
    float* psum = (float*)(smem + OFF_PSUM);
    int*   stile = (int*)(smem + OFF_TILE);

    // Stage W2 hi/lo into padded SMEM + b2/W3, once.
    {
        const uint4* shi = (const uint4*)g_W2hi;
        const uint4* slo = (const uint4*)g_W2lo;
        for (int i = tid; i < 2048; i += 256) {       // 128 rows x 16 uint4
            int r = i >> 4, c = i & 15;
            *(uint4*)(smem + OFF_BHI + r * STB + c * 16) = shi[i];
            *(uint4*)(smem + OFF_BLO + r * STB + c * 16) = slo[i];
        }
        if (tid < 128) { b2s[tid] = b2[tid]; w3s[tid] = W3[tid]; }
    }
    const float bias3 = b3[0];

    // Warp tiling: 4 (M) x 2 (N); each warp owns 32 rows x 64 cols.
    const int mwb   = (wid & 3) * 32;
    const int nh    = wid >> 2;
    const int nbase = nh * 64;

    // h1-stage mapping: warp-uniform k-half for broadcast uc reads
    const int hrow = tid & 127;
    const int hkh  = (tid >> 7) * 64;

    for (;;) {
        if (tid == 0) stile[0] = atomicAdd(&g_tile_ctr, 1);
        __syncthreads();
        const int tile = stile[0];
        if (tile >= NUM_TILES) break;

        const int b   = tile >> 8;
        const int rem = tile & 255;
        const int u   = rem >> 1;
        const int th  = rem & 1;

        // uc[k] = ue_proj[b,u,k] + (ge@W1g + b1)[b,k]
        if (tid < 128)
            uc[tid] = g_ue_proj[(b * UU + u) * HH + tid] + g_gcomb[b * HH + tid];
        __syncthreads();

        // ---- h1 stage: gelu + bf16 hi/lo split into SMEM A tiles ----
        {
            const float* terow =
                g_te_proj + ((size_t)(b * TT + th * 128 + hrow)) * HH + hkh;
            const float* ucp = uc + hkh;
            char* arow_hi = smem + OFF_AHI + hrow * STB + hkh * 2;
            char* arow_lo = smem + OFF_ALO + hrow * STB + hkh * 2;
#pragma unroll
            for (int c8 = 0; c8 < 64; c8 += 8) {
                float4 t0 = *(const float4*)(terow + c8);
                float4 t1 = *(const float4*)(terow + c8 + 4);
                float v0 = gelu_f(t0.x + ucp[c8 + 0]);
                float v1 = gelu_f(t0.y + ucp[c8 + 1]);
                float v2 = gelu_f(t0.z + ucp[c8 + 2]);
                float v3 = gelu_f(t0.w + ucp[c8 + 3]);
                float v4 = gelu_f(t1.x + ucp[c8 + 4]);
                float v5 = gelu_f(t1.y + ucp[c8 + 5]);
                float v6 = gelu_f(t1.z + ucp[c8 + 6]);
                float v7 = gelu_f(t1.w + ucp[c8 + 7]);
                uint32_t h0, h1w, h2w, h3w, l0, l1, l2, l3;
                split2(v0, v1, h0, l0);
                split2(v2, v3, h1w, l1);
                split2(v4, v5, h2w, l2);
                split2(v6, v7, h3w, l3);
                *(uint4*)(arow_hi + c8 * 2) = make_uint4(h0, h1w, h2w, h3w);
                *(uint4*)(arow_lo + c8 * 2) = make_uint4(l0, l1, l2, l3);
            }
        }
        __syncthreads();

        // ---- GEMM: D = Ahi*Bhi + Alo*Bhi + Ahi*Blo (fp32 accum in regs) ----
        float acc[2][8][4];
#pragma unroll
        for (int mt = 0; mt < 2; mt++)
#pragma unroll
            for (int nt = 0; nt < 8; nt++)
#pragma unroll
                for (int i = 0; i < 4; i++) acc[mt][nt][i] = 0.0f;

        // ldmatrix lane addressing
        const int a_r  = mwb + (lane & 15);           // A row for this lane
        const int a_kb = ((lane >> 4) & 1) * 8;       // A k-subcolumn (0/8)
        const int b_r  = nbase + (lane & 7);          // B row (n) for this lane
        const int b_kb = ((lane >> 3) & 1) * 8;       // B k-subcolumn (0/8)

        for (int kt = 0; kt < 8; kt++) {
            const int k0 = kt * 16;
            uint32_t ahi[2][4], alo[2][4];
#pragma unroll
            for (int mt = 0; mt < 2; mt++) {
                uint32_t aaddr = smem_base + (a_r + mt * 16) * STB + (k0 + a_kb) * 2;
                ldmatrix_x4(ahi[mt][0], ahi[mt][1], ahi[mt][2], ahi[mt][3],
                            aaddr + OFF_AHI);
                ldmatrix_x4(alo[mt][0], alo[mt][1], alo[mt][2], alo[mt][3],
                            aaddr + OFF_ALO);
            }
            uint32_t bhi[8][2], blo[8][2];
#pragma unroll
            for (int nt = 0; nt < 8; nt++) {
                uint32_t baddr = smem_base + (b_r + nt * 8) * STB + (k0 + b_kb) * 2;
                ldmatrix_x2(bhi[nt][0], bhi[nt][1], baddr + OFF_BHI);
                ldmatrix_x2(blo[nt][0], blo[nt][1], baddr + OFF_BLO);
            }
#pragma unroll
            for (int mt = 0; mt < 2; mt++)
#pragma unroll
                for (int nt = 0; nt < 8; nt++) {
                    mma_bf16(acc[mt][nt], ahi[mt], bhi[nt]);
                    mma_bf16(acc[mt][nt], alo[mt], bhi[nt]);
                    mma_bf16(acc[mt][nt], ahi[mt], blo[nt]);
                }
        }

        // ---- Epilogue: gelu(acc + b2) . W3, reduce over N ----
        {
            float b2v[16], w3v[16];
#pragma unroll
            for (int nt = 0; nt < 8; nt++)
#pragma unroll
                for (int j = 0; j < 2; j++) {
                    int col = nbase + nt * 8 + 2 * (lane & 3) + j;
                    b2v[nt * 2 + j] = b2s[col];
                    w3v[nt * 2 + j] = w3s[col];
                }
#pragma unroll
            for (int mt = 0; mt < 2; mt++)
#pragma unroll
                for (int ih = 0; ih < 2; ih++) {
                    float s = 0.0f;
#pragma unroll
                    for (int nt = 0; nt < 8; nt++)
#pragma unroll
                        for (int j = 0; j < 2; j++) {
                            float v = acc[mt][nt][ih * 2 + j];
                            s = fmaf(gelu_f(v + b2v[nt * 2 + j]),
                                     w3v[nt * 2 + j], s);
                        }
                    s += __shfl_xor_sync(0xffffffffu, s, 1);
                    s += __shfl_xor_sync(0xffffffffu, s, 2);
                    if ((lane & 3) == 0) {
                        int row = mwb + mt * 16 + ih * 8 + (lane >> 2);
                        psum[nh * 128 + row] = s;
                    }
                }
        }
        __syncthreads();
        if (tid < 128) {
            out[(size_t)b * (UU * TT) + u * TT + th * 128 + tid] =
                psum[tid] + psum[128 + tid] + bias3;
        }
        __syncthreads();
    }
}

// ---------------------------------------------------------------------------
// Launch
// ---------------------------------------------------------------------------
extern "C" void kernel_launch(void* const* d_in, const int* in_sizes, int n_in,
                              void* d_out, int out_size) {
    (void)in_sizes; (void)n_in; (void)out_size;
    const float* ue = (const float*)d_in[0];
    const float* te = (const float*)d_in[1];
    const float* ge = (const float*)d_in[2];
    const float* W1 = (const float*)d_in[3];
    const float* b1 = (const float*)d_in[4];
    const float* W2 = (const float*)d_in[5];
    const float* b2 = (const float*)d_in[6];
    const float* W3 = (const float*)d_in[7];
    const float* b3 = (const float*)d_in[8];
    float* out = (float*)d_out;

    cudaFuncSetAttribute(pairwise_main,
                         cudaFuncAttributeMaxDynamicSharedMemorySize, SMEM_MAIN);

    proj_kernel<<<97, 128>>>(ue, te, ge, W1, b1);
    prep_w2_kernel<<<1, 128>>>(W2);
    pairwise_main<<<152, 256, SMEM_MAIN>>>(b2, W3, b3, out);
}

// round 4
// speedup vs baseline: 1.1282x; 1.1282x over previous
#include <cuda_runtime.h>
#include <cuda_fp16.h>
#include <cstdint>

// ---------------------------------------------------------------------------
// Problem dims
// ---------------------------------------------------------------------------
#define BB 8
#define UU 128
#define TT 256
#define EE 128
#define HH 128
#define NUM_TILES (BB * UU * 2)          // 2048 tiles of 128 t-rows each

// ---------------------------------------------------------------------------
// Device scratch (no allocs allowed)
// ---------------------------------------------------------------------------
__device__ __align__(16) float g_ue_proj[BB * UU * HH];     // ue @ W1u
__device__ __align__(16) float g_te_proj[BB * TT * HH];     // te @ W1t
__device__ __align__(16) float g_gcomb[BB * HH];            // ge @ W1g + b1
__device__ __align__(16) __half g_W2hi[HH * HH];            // W2^T hi [n][k]
__device__ __align__(16) __half g_W2lo[HH * HH];            // W2^T lo [n][k]
__device__ __align__(16) float2 g_tbl[1536];                // gelu PW-linear LUT
__device__ int g_tile_ctr;

// ---------------------------------------------------------------------------
// PTX helpers (plain sm_103-safe: ldmatrix + mma.sync only)
// ---------------------------------------------------------------------------
__device__ __forceinline__ uint32_t smem_to_u32(const void* p) {
    uint32_t a;
    asm("{ .reg .u64 t; cvta.to.shared.u64 t, %1; cvt.u32.u64 %0, t; }"
        : "=r"(a) : "l"(p));
    return a;
}

__device__ __forceinline__ void ldmatrix_x4(uint32_t& r0, uint32_t& r1,
                                            uint32_t& r2, uint32_t& r3,
                                            uint32_t addr) {
    asm volatile("ldmatrix.sync.aligned.m8n8.x4.shared.b16 {%0,%1,%2,%3}, [%4];"
                 : "=r"(r0), "=r"(r1), "=r"(r2), "=r"(r3) : "r"(addr));
}
__device__ __forceinline__ void ldmatrix_x2(uint32_t& r0, uint32_t& r1,
                                            uint32_t addr) {
    asm volatile("ldmatrix.sync.aligned.m8n8.x2.shared.b16 {%0,%1}, [%2];"
                 : "=r"(r0), "=r"(r1) : "r"(addr));
}

__device__ __forceinline__ void mma_fp16(float* c, const uint32_t* a,
                                         const uint32_t* b) {
    asm volatile(
        "mma.sync.aligned.m16n8k16.row.col.f32.f16.f16.f32 "
        "{%0,%1,%2,%3}, {%4,%5,%6,%7}, {%8,%9}, {%0,%1,%2,%3};"
        : "+f"(c[0]), "+f"(c[1]), "+f"(c[2]), "+f"(c[3])
        : "r"(a[0]), "r"(a[1]), "r"(a[2]), "r"(a[3]), "r"(b[0]), "r"(b[1]));
}

// ---------------------------------------------------------------------------
// Math helpers
// ---------------------------------------------------------------------------
__device__ __forceinline__ float gelu_exact(float x) {
    return 0.5f * x * (1.0f + erff(x * 0.70710678118654752f));
}

// LUT gelu: piecewise-linear over [-6,6], 1536 cells of width 1/128.
__device__ __forceinline__ float gelu_lut(float x, const float2* __restrict__ t) {
    float u = fmaf(x, 128.0f, 768.0f);
    u = fminf(fmaxf(u, 0.0f), 1535.969f);
    int   i  = __float2int_rd(u);
    float fr = u - (float)i;
    float2 e = t[i];
    float y  = fmaf(e.y, fr, e.x);
    y = (x >= 6.0f) ? x : y;
    y = (x <= -6.0f) ? 0.0f : y;
    return y;
}

__device__ __forceinline__ uint32_t packh2(float a, float b) {
    __half2 h = __floats2half2_rn(a, b);
    return *reinterpret_cast<uint32_t*>(&h);
}

// ---------------------------------------------------------------------------
// Unified prep kernel, 394 blocks x 128 threads:
//   0..127   : ue rows (8/block)        -> g_ue_proj
//   128..383 : te rows (8/block)        -> g_te_proj
//   384      : ge rows (8) + b1         -> g_gcomb
//   385..392 : W2 fp16 hi/lo split      -> g_W2hi/g_W2lo  ([n][k])
//   393      : gelu LUT + tile counter reset
// ---------------------------------------------------------------------------
__global__ __launch_bounds__(128) void prep_kernel(
    const float* __restrict__ ue, const float* __restrict__ te,
    const float* __restrict__ ge, const float* __restrict__ W1,
    const float* __restrict__ b1, const float* __restrict__ W2) {
    __shared__ float s_in[8 * EE];
    const int bid = blockIdx.x;
    const int tid = threadIdx.x;

    if (bid < 385) {
        const float* src;
        float* dst;
        const float* W;
        bool add_b1 = false;
        if (bid < 128) {
            src = ue + bid * 8 * EE;  dst = g_ue_proj + bid * 8 * HH;  W = W1;
        } else if (bid < 384) {
            int r = bid - 128;
            src = te + r * 8 * EE;    dst = g_te_proj + r * 8 * HH;
            W = W1 + EE * HH;
        } else {
            src = ge;  dst = g_gcomb;  W = W1 + 2 * EE * HH;  add_b1 = true;
        }
        for (int i = tid; i < 8 * EE; i += 128) s_in[i] = src[i];
        __syncthreads();

        float acc[8];
        float bb = add_b1 ? b1[tid] : 0.0f;
#pragma unroll
        for (int r = 0; r < 8; r++) acc[r] = bb;
#pragma unroll 4
        for (int e = 0; e < EE; e++) {
            float w = W[e * HH + tid];
#pragma unroll
            for (int r = 0; r < 8; r++)
                acc[r] = fmaf(s_in[r * EE + e], w, acc[r]);
        }
#pragma unroll
        for (int r = 0; r < 8; r++) dst[r * HH + tid] = acc[r];
    } else if (bid < 393) {
        // W2 split: n-range [n0, n0+16)
        int n0 = (bid - 385) * 16;
        for (int r = 0; r < 16; r++) {
            int n = n0 + r;
            float w = W2[tid * HH + n];
            __half hi = __float2half_rn(w);
            float lof = w - __half2float(hi);
            g_W2hi[n * HH + tid] = hi;
            g_W2lo[n * HH + tid] = __float2half_rn(lof);
        }
    } else {
        if (tid == 0) g_tile_ctr = 0;
        for (int i = tid; i < 1536; i += 128) {
            float x0 = -6.0f + (float)i * (1.0f / 128.0f);
            float v0 = gelu_exact(x0);
            float v1 = gelu_exact(x0 + (1.0f / 128.0f));
            g_tbl[i] = make_float2(v0, v1 - v0);
        }
    }
}

// ---------------------------------------------------------------------------
// Main fused kernel (persistent, 16 warps, HMMA fp16 2-product):
//   per tile (b,u,thalf): h1 = gelu_lut(uc + te_proj) -> fp16 A tile in SMEM
//   -> D = A*W2hi + A*W2lo (fp32 accum in regs)
//   -> +b2, gelu_lut, dot W3, +b3 -> out
// ---------------------------------------------------------------------------
static constexpr int ST      = 136;                 // row stride in fp16
static constexpr int STB     = ST * 2;              // 272 bytes
static constexpr int TILE_B  = 128 * STB;           // 34816
static constexpr int OFF_A   = 0;
static constexpr int OFF_BHI = OFF_A + TILE_B;
static constexpr int OFF_BLO = OFF_BHI + TILE_B;
static constexpr int OFF_TBL = OFF_BLO + TILE_B;    // 1536 float2 = 12288
static constexpr int OFF_B2S = OFF_TBL + 12288;     // 128 floats
static constexpr int OFF_W3S = OFF_B2S + 512;       // 128 floats
static constexpr int OFF_PSUM = OFF_W3S + 512;      // 512 floats
static constexpr int OFF_TILE = OFF_PSUM + 2048;
static constexpr int SMEM_MAIN = OFF_TILE + 16;

__global__ __launch_bounds__(512, 1) void pairwise_main(
    const float* __restrict__ b2, const float* __restrict__ W3,
    const float* __restrict__ b3, float* __restrict__ out) {
    extern __shared__ char smem[];
    const uint32_t smem_base = smem_to_u32(smem);
    const int tid  = threadIdx.x;
    const int wid  = tid >> 5;
    const int lane = tid & 31;

    const float2* tbl = (const float2*)(smem + OFF_TBL);
    float* b2s  = (float*)(smem + OFF_B2S);
    float* w3s  = (float*)(smem + OFF_W3S);
    float* psum = (float*)(smem + OFF_PSUM);
    int*   stile = (int*)(smem + OFF_TILE);

    // Stage W2 hi/lo (padded rows) + LUT + b2/W3 into SMEM, once.
    {
        const uint4* shi = (const uint4*)g_W2hi;
        const uint4* slo = (const uint4*)g_W2lo;
        for (int i = tid; i < 2048; i += 512) {       // 128 rows x 16 uint4
            int r = i >> 4, c = i & 15;
            *(uint4*)(smem + OFF_BHI + r * STB + c * 16) = shi[i];
            *(uint4*)(smem + OFF_BLO + r * STB + c * 16) = slo[i];
        }
        const uint4* st = (const uint4*)g_tbl;
        for (int i = tid; i < 768; i += 512)
            *((uint4*)(smem + OFF_TBL) + i) = st[i];
        if (tid < 128) { b2s[tid] = b2[tid]; w3s[tid] = W3[tid]; }
    }
    const float bias3 = b3[0];

    // Warp tiling: 4 (M) x 4 (N); each warp owns 32 rows x 32 cols.
    const int mwb   = (wid & 3) * 32;
    const int nq    = wid >> 2;
    const int nbase = nq * 32;

    // h1-stage mapping: 4 threads per row, 32 k-cols each
    const int hrow = tid & 127;
    const int hkq  = (tid >> 7) * 32;

    // ldmatrix lane addressing
    const int a_r = mwb + (lane & 15);
    const int a_k = ((lane >> 4) & 1) * 8;
    const int b_r = nbase + (lane & 7);
    const int b_k = ((lane >> 3) & 1) * 8;

    __syncthreads();

    for (;;) {
        if (tid == 0) stile[0] = atomicAdd(&g_tile_ctr, 1);
        __syncthreads();
        const int tile = stile[0];
        if (tile >= NUM_TILES) break;

        const int b   = tile >> 8;
        const int rem = tile & 255;
        const int u   = rem >> 1;
        const int th  = rem & 1;

        // ---- h1 stage: gelu_lut(te_proj + ue_proj + gcomb) -> fp16 A ----
        {
            const float* terow =
                g_te_proj + ((size_t)(b * TT + th * 128 + hrow)) * HH + hkq;
            const float* uep = g_ue_proj + (b * UU + u) * HH + hkq;
            const float* gcp = g_gcomb + b * HH + hkq;
            char* arow = smem + OFF_A + hrow * STB + hkq * 2;
#pragma unroll
            for (int c8 = 0; c8 < 32; c8 += 8) {
                float4 t0 = *(const float4*)(terow + c8);
                float4 t1 = *(const float4*)(terow + c8 + 4);
                float4 u0 = *(const float4*)(uep + c8);
                float4 u1 = *(const float4*)(uep + c8 + 4);
                float4 g0 = *(const float4*)(gcp + c8);
                float4 g1 = *(const float4*)(gcp + c8 + 4);
                float v0 = gelu_lut(t0.x + u0.x + g0.x, tbl);
                float v1 = gelu_lut(t0.y + u0.y + g0.y, tbl);
                float v2 = gelu_lut(t0.z + u0.z + g0.z, tbl);
                float v3 = gelu_lut(t0.w + u0.w + g0.w, tbl);
                float v4 = gelu_lut(t1.x + u1.x + g1.x, tbl);
                float v5 = gelu_lut(t1.y + u1.y + g1.y, tbl);
                float v6 = gelu_lut(t1.z + u1.z + g1.z, tbl);
                float v7 = gelu_lut(t1.w + u1.w + g1.w, tbl);
                *(uint4*)(arow + c8 * 2) =
                    make_uint4(packh2(v0, v1), packh2(v2, v3),
                               packh2(v4, v5), packh2(v6, v7));
            }
        }
        __syncthreads();

        // ---- GEMM: D = A*Bhi + A*Blo (fp32 accum in regs) ----
        float acc[2][4][4];
#pragma unroll
        for (int mt = 0; mt < 2; mt++)
#pragma unroll
            for (int nt = 0; nt < 4; nt++)
#pragma unroll
                for (int i = 0; i < 4; i++) acc[mt][nt][i] = 0.0f;

#pragma unroll
        for (int kt = 0; kt < 8; kt++) {
            const int k0 = kt * 16;
            uint32_t a[2][4];
#pragma unroll
            for (int mt = 0; mt < 2; mt++) {
                uint32_t aaddr =
                    smem_base + OFF_A + (a_r + mt * 16) * STB + (k0 + a_k) * 2;
                ldmatrix_x4(a[mt][0], a[mt][1], a[mt][2], a[mt][3], aaddr);
            }
            uint32_t bh[4][2], bl[4][2];
#pragma unroll
            for (int nt = 0; nt < 4; nt++) {
                uint32_t boff = (b_r + nt * 8) * STB + (k0 + b_k) * 2;
                ldmatrix_x2(bh[nt][0], bh[nt][1], smem_base + OFF_BHI + boff);
                ldmatrix_x2(bl[nt][0], bl[nt][1], smem_base + OFF_BLO + boff);
            }
#pragma unroll
            for (int mt = 0; mt < 2; mt++)
#pragma unroll
                for (int nt = 0; nt < 4; nt++) {
                    mma_fp16(acc[mt][nt], a[mt], bh[nt]);
                    mma_fp16(acc[mt][nt], a[mt], bl[nt]);
                }
        }

        // ---- Epilogue: gelu_lut(acc + b2) . W3, reduce over N ----
        {
            float b2v[8], w3v[8];
#pragma unroll
            for (int nt = 0; nt < 4; nt++)
#pragma unroll
                for (int j = 0; j < 2; j++) {
                    int col = nbase + nt * 8 + 2 * (lane & 3) + j;
                    b2v[nt * 2 + j] = b2s[col];
                    w3v[nt * 2 + j] = w3s[col];
                }
#pragma unroll
            for (int mt = 0; mt < 2; mt++)
#pragma unroll
                for (int ih = 0; ih < 2; ih++) {
                    float s = 0.0f;
#pragma unroll
                    for (int nt = 0; nt < 4; nt++)
#pragma unroll
                        for (int j = 0; j < 2; j++) {
                            float v = acc[mt][nt][ih * 2 + j];
                            s = fmaf(gelu_lut(v + b2v[nt * 2 + j], tbl),
                                     w3v[nt * 2 + j], s);
                        }
                    s += __shfl_xor_sync(0xffffffffu, s, 1);
                    s += __shfl_xor_sync(0xffffffffu, s, 2);
                    if ((lane & 3) == 0) {
                        int row = mwb + mt * 16 + ih * 8 + (lane >> 2);
                        psum[nq * 128 + row] = s;
                    }
                }
        }
        __syncthreads();
        if (tid < 128) {
            out[(size_t)b * (UU * TT) + u * TT + th * 128 + tid] =
                psum[tid] + psum[128 + tid] + psum[256 + tid] + psum[384 + tid]
                + bias3;
        }
        __syncthreads();
    }
}

// ---------------------------------------------------------------------------
// Launch
// ---------------------------------------------------------------------------
extern "C" void kernel_launch(void* const* d_in, const int* in_sizes, int n_in,
                              void* d_out, int out_size) {
    (void)in_sizes; (void)n_in; (void)out_size;
    const float* ue = (const float*)d_in[0];
    const float* te = (const float*)d_in[1];
    const float* ge = (const float*)d_in[2];
    const float* W1 = (const float*)d_in[3];
    const float* b1 = (const float*)d_in[4];
    const float* W2 = (const float*)d_in[5];
    const float* b2 = (const float*)d_in[6];
    const float* W3 = (const float*)d_in[7];
    const float* b3 = (const float*)d_in[8];
    float* out = (float*)d_out;

    cudaFuncSetAttribute(pairwise_main,
                         cudaFuncAttributeMaxDynamicSharedMemorySize, SMEM_MAIN);

    prep_kernel<<<394, 128>>>(ue, te, ge, W1, b1, W2);
    pairwise_main<<<152, 512, SMEM_MAIN>>>(b2, W3, b3, out);
}

// round 5
// speedup vs baseline: 1.3693x; 1.2137x over previous
#include <cuda_runtime.h>
#include <cuda_fp16.h>
#include <cstdint>

// ---------------------------------------------------------------------------
// Problem dims
// ---------------------------------------------------------------------------
#define BB 8
#define UU 128
#define TT 256
#define EE 128
#define HH 128
#define NUM_TILES (BB * UU * 2)          // 2048 tiles of 128 t-rows each

// ---------------------------------------------------------------------------
// Device scratch (no allocs allowed)
// ---------------------------------------------------------------------------
__device__ __align__(16) float g_ue_proj[BB * UU * HH];     // ue @ W1u
__device__ __align__(16) float g_te_proj[BB * TT * HH];     // te @ W1t
__device__ __align__(16) float g_gcomb[BB * HH];            // ge @ W1g + b1
__device__ __align__(16) __half g_W2h[HH * HH];             // W2^T fp16 [n][k]
__device__ __align__(16) float2 g_tbl[1536];                // gelu PW-linear LUT
__device__ int g_tile_ctr;

// ---------------------------------------------------------------------------
// PTX helpers (plain sm_103-safe: ldmatrix + mma.sync only)
// ---------------------------------------------------------------------------
__device__ __forceinline__ uint32_t smem_to_u32(const void* p) {
    uint32_t a;
    asm("{ .reg .u64 t; cvta.to.shared.u64 t, %1; cvt.u32.u64 %0, t; }"
        : "=r"(a) : "l"(p));
    return a;
}

__device__ __forceinline__ void ldmatrix_x4(uint32_t& r0, uint32_t& r1,
                                            uint32_t& r2, uint32_t& r3,
                                            uint32_t addr) {
    asm volatile("ldmatrix.sync.aligned.m8n8.x4.shared.b16 {%0,%1,%2,%3}, [%4];"
                 : "=r"(r0), "=r"(r1), "=r"(r2), "=r"(r3) : "r"(addr));
}
__device__ __forceinline__ void ldmatrix_x2(uint32_t& r0, uint32_t& r1,
                                            uint32_t addr) {
    asm volatile("ldmatrix.sync.aligned.m8n8.x2.shared.b16 {%0,%1}, [%2];"
                 : "=r"(r0), "=r"(r1) : "r"(addr));
}

__device__ __forceinline__ void mma_fp16(float* c, const uint32_t* a,
                                         const uint32_t* b) {
    asm volatile(
        "mma.sync.aligned.m16n8k16.row.col.f32.f16.f16.f32 "
        "{%0,%1,%2,%3}, {%4,%5,%6,%7}, {%8,%9}, {%0,%1,%2,%3};"
        : "+f"(c[0]), "+f"(c[1]), "+f"(c[2]), "+f"(c[3])
        : "r"(a[0]), "r"(a[1]), "r"(a[2]), "r"(a[3]), "r"(b[0]), "r"(b[1]));
}

// ---------------------------------------------------------------------------
// Math helpers
// ---------------------------------------------------------------------------
__device__ __forceinline__ float gelu_exact(float x) {
    return 0.5f * x * (1.0f + erff(x * 0.70710678118654752f));
}

// LUT gelu: piecewise-linear over [-6,6], 1536 cells of width 1/128.
__device__ __forceinline__ float gelu_lut(float x, const float2* __restrict__ t) {
    float u = fmaf(x, 128.0f, 768.0f);
    u = fminf(fmaxf(u, 0.0f), 1535.969f);
    int   i  = __float2int_rd(u);
    float fr = u - (float)i;
    float2 e = t[i];
    float y  = fmaf(e.y, fr, e.x);
    y = (x >= 6.0f) ? x : y;
    y = (x <= -6.0f) ? 0.0f : y;
    return y;
}

__device__ __forceinline__ uint32_t packh2(float a, float b) {
    __half2 h = __floats2half2_rn(a, b);
    return *reinterpret_cast<uint32_t*>(&h);
}

// ---------------------------------------------------------------------------
// Unified prep kernel, 394 blocks x 128 threads:
//   0..127   : ue rows (8/block)   -> g_ue_proj
//   128..383 : te rows (8/block)   -> g_te_proj
//   384      : ge rows (8) + b1    -> g_gcomb
//   385..392 : W2 fp16 transpose   -> g_W2h ([n][k])
//   393      : gelu LUT + tile counter reset
// ---------------------------------------------------------------------------
__global__ __launch_bounds__(128) void prep_kernel(
    const float* __restrict__ ue, const float* __restrict__ te,
    const float* __restrict__ ge, const float* __restrict__ W1,
    const float* __restrict__ b1, const float* __restrict__ W2) {
    __shared__ float s_in[8 * EE];
    const int bid = blockIdx.x;
    const int tid = threadIdx.x;

    if (bid < 385) {
        const float* src;
        float* dst;
        const float* W;
        bool add_b1 = false;
        if (bid < 128) {
            src = ue + bid * 8 * EE;  dst = g_ue_proj + bid * 8 * HH;  W = W1;
        } else if (bid < 384) {
            int r = bid - 128;
            src = te + r * 8 * EE;    dst = g_te_proj + r * 8 * HH;
            W = W1 + EE * HH;
        } else {
            src = ge;  dst = g_gcomb;  W = W1 + 2 * EE * HH;  add_b1 = true;
        }
        for (int i = tid; i < 8 * EE; i += 128) s_in[i] = src[i];
        __syncthreads();

        float acc[8];
        float bb = add_b1 ? b1[tid] : 0.0f;
#pragma unroll
        for (int r = 0; r < 8; r++) acc[r] = bb;
#pragma unroll 4
        for (int e = 0; e < EE; e++) {
            float w = W[e * HH + tid];
#pragma unroll
            for (int r = 0; r < 8; r++)
                acc[r] = fmaf(s_in[r * EE + e], w, acc[r]);
        }
#pragma unroll
        for (int r = 0; r < 8; r++) dst[r * HH + tid] = acc[r];
    } else if (bid < 393) {
        int n0 = (bid - 385) * 16;
        for (int r = 0; r < 16; r++) {
            int n = n0 + r;
            g_W2h[n * HH + tid] = __float2half_rn(W2[tid * HH + n]);
        }
    } else {
        if (tid == 0) g_tile_ctr = 0;
        for (int i = tid; i < 1536; i += 128) {
            float x0 = -6.0f + (float)i * (1.0f / 128.0f);
            float v0 = gelu_exact(x0);
            float v1 = gelu_exact(x0 + (1.0f / 128.0f));
            g_tbl[i] = make_float2(v0, v1 - v0);
        }
    }
}

// ---------------------------------------------------------------------------
// Main fused kernel (persistent, 8 warps/CTA, 2 CTAs/SM, fp16 HMMA):
//   per tile (b,u,thalf): h1 = gelu_lut(uc + te_proj) -> fp16 A in SMEM
//   -> D = A * W2h (fp32 accum in regs) -> +b2, gelu_lut, dot W3, +b3 -> out
// ---------------------------------------------------------------------------
static constexpr int ST      = 136;                 // row stride in fp16
static constexpr int STB     = ST * 2;              // 272 bytes
static constexpr int TILE_BY = 128 * STB;           // 34816
static constexpr int OFF_A   = 0;
static constexpr int OFF_B   = OFF_A + TILE_BY;
static constexpr int OFF_TBL = OFF_B + TILE_BY;     // 12288
static constexpr int OFF_UC  = OFF_TBL + 12288;     // 128 floats
static constexpr int OFF_B2S = OFF_UC + 512;        // 128 floats
static constexpr int OFF_W3S = OFF_B2S + 512;       // 128 floats
static constexpr int OFF_PSUM = OFF_W3S + 512;      // 256 floats
static constexpr int OFF_TILE = OFF_PSUM + 1024;
static constexpr int SMEM_MAIN = OFF_TILE + 16;     // ~84 KB -> 2 CTAs/SM

__global__ __launch_bounds__(256, 2) void pairwise_main(
    const float* __restrict__ b2, const float* __restrict__ W3,
    const float* __restrict__ b3, float* __restrict__ out) {
    extern __shared__ char smem[];
    const uint32_t smem_base = smem_to_u32(smem);
    const int tid  = threadIdx.x;
    const int wid  = tid >> 5;
    const int lane = tid & 31;

    const float2* tbl = (const float2*)(smem + OFF_TBL);
    float* uc   = (float*)(smem + OFF_UC);
    float* b2s  = (float*)(smem + OFF_B2S);
    float* w3s  = (float*)(smem + OFF_W3S);
    float* psum = (float*)(smem + OFF_PSUM);
    int*   stile = (int*)(smem + OFF_TILE);

    // Stage W2 (padded rows) + LUT + b2/W3 into SMEM, once.
    {
        const uint4* sb = (const uint4*)g_W2h;
        for (int i = tid; i < 2048; i += 256) {       // 128 rows x 16 uint4
            int r = i >> 4, c = i & 15;
            *(uint4*)(smem + OFF_B + r * STB + c * 16) = sb[i];
        }
        const uint4* st = (const uint4*)g_tbl;
        for (int i = tid; i < 768; i += 256)
            *((uint4*)(smem + OFF_TBL) + i) = st[i];
        if (tid < 128) { b2s[tid] = b2[tid]; w3s[tid] = W3[tid]; }
    }
    const float bias3 = b3[0];

    // Warp tiling: 4 (M) x 2 (N); each warp owns 32 rows x 64 cols.
    const int mwb   = (wid & 3) * 32;
    const int nh    = wid >> 2;
    const int nbase = nh * 64;

    // h1-stage mapping: 2 threads per row, 64 k-cols each (k-half warp-uniform)
    const int hrow = tid & 127;
    const int hkh  = (tid >> 7) * 64;

    // ldmatrix lane addressing
    const int a_r = mwb + (lane & 15);
    const int a_k = ((lane >> 4) & 1) * 8;
    const int b_r = nbase + (lane & 7);
    const int b_k = ((lane >> 3) & 1) * 8;

    __syncthreads();

    for (;;) {
        if (tid == 0) stile[0] = atomicAdd(&g_tile_ctr, 1);
        __syncthreads();
        const int tile = stile[0];
        if (tile >= NUM_TILES) break;

        const int b   = tile >> 8;
        const int rem = tile & 255;
        const int u   = rem >> 1;
        const int th  = rem & 1;

        // uc[k] = ue_proj[b,u,k] + (ge@W1g + b1)[b,k]
        if (tid < 128)
            uc[tid] = g_ue_proj[(b * UU + u) * HH + tid] + g_gcomb[b * HH + tid];
        __syncthreads();

        // ---- h1 stage: gelu_lut(te_proj + uc) -> fp16 A tile ----
        {
            const float* terow =
                g_te_proj + ((size_t)(b * TT + th * 128 + hrow)) * HH + hkh;
            const float* ucp = uc + hkh;
            char* arow = smem + OFF_A + hrow * STB + hkh * 2;
#pragma unroll
            for (int c8 = 0; c8 < 64; c8 += 8) {
                float4 t0 = *(const float4*)(terow + c8);
                float4 t1 = *(const float4*)(terow + c8 + 4);
                float4 u0 = *(const float4*)(ucp + c8);
                float4 u1 = *(const float4*)(ucp + c8 + 4);
                float v0 = gelu_lut(t0.x + u0.x, tbl);
                float v1 = gelu_lut(t0.y + u0.y, tbl);
                float v2 = gelu_lut(t0.z + u0.z, tbl);
                float v3 = gelu_lut(t0.w + u0.w, tbl);
                float v4 = gelu_lut(t1.x + u1.x, tbl);
                float v5 = gelu_lut(t1.y + u1.y, tbl);
                float v6 = gelu_lut(t1.z + u1.z, tbl);
                float v7 = gelu_lut(t1.w + u1.w, tbl);
                *(uint4*)(arow + c8 * 2) =
                    make_uint4(packh2(v0, v1), packh2(v2, v3),
                               packh2(v4, v5), packh2(v6, v7));
            }
        }
        __syncthreads();

        // ---- GEMM: D = A * W2h (fp32 accum in regs) ----
        float acc[2][8][4];
#pragma unroll
        for (int mt = 0; mt < 2; mt++)
#pragma unroll
            for (int nt = 0; nt < 8; nt++)
#pragma unroll
                for (int i = 0; i < 4; i++) acc[mt][nt][i] = 0.0f;

#pragma unroll
        for (int kt = 0; kt < 8; kt++) {
            const int k0 = kt * 16;
            uint32_t a[2][4];
#pragma unroll
            for (int mt = 0; mt < 2; mt++) {
                uint32_t aaddr =
                    smem_base + OFF_A + (a_r + mt * 16) * STB + (k0 + a_k) * 2;
                ldmatrix_x4(a[mt][0], a[mt][1], a[mt][2], a[mt][3], aaddr);
            }
            uint32_t bh[8][2];
#pragma unroll
            for (int nt = 0; nt < 8; nt++) {
                uint32_t baddr =
                    smem_base + OFF_B + (b_r + nt * 8) * STB + (k0 + b_k) * 2;
                ldmatrix_x2(bh[nt][0], bh[nt][1], baddr);
            }
#pragma unroll
            for (int mt = 0; mt < 2; mt++)
#pragma unroll
                for (int nt = 0; nt < 8; nt++)
                    mma_fp16(acc[mt][nt], a[mt], bh[nt]);
        }

        // ---- Epilogue: gelu_lut(acc + b2) . W3, reduce over N ----
        {
            float b2v[16], w3v[16];
#pragma unroll
            for (int nt = 0; nt < 8; nt++)
#pragma unroll
                for (int j = 0; j < 2; j++) {
                    int col = nbase + nt * 8 + 2 * (lane & 3) + j;
                    b2v[nt * 2 + j] = b2s[col];
                    w3v[nt * 2 + j] = w3s[col];
                }
#pragma unroll
            for (int mt = 0; mt < 2; mt++)
#pragma unroll
                for (int ih = 0; ih < 2; ih++) {
                    float s = 0.0f;
#pragma unroll
                    for (int nt = 0; nt < 8; nt++)
#pragma unroll
                        for (int j = 0; j < 2; j++) {
                            float v = acc[mt][nt][ih * 2 + j];
                            s = fmaf(gelu_lut(v + b2v[nt * 2 + j], tbl),
                                     w3v[nt * 2 + j], s);
                        }
                    s += __shfl_xor_sync(0xffffffffu, s, 1);
                    s += __shfl_xor_sync(0xffffffffu, s, 2);
                    if ((lane & 3) == 0) {
                        int row = mwb + mt * 16 + ih * 8 + (lane >> 2);
                        psum[nh * 128 + row] = s;
                    }
                }
        }
        __syncthreads();
        if (tid < 128) {
            out[(size_t)b * (UU * TT) + u * TT + th * 128 + tid] =
                psum[tid] + psum[128 + tid] + bias3;
        }
        __syncthreads();
    }
}

// ---------------------------------------------------------------------------
// Launch
// ---------------------------------------------------------------------------
extern "C" void kernel_launch(void* const* d_in, const int* in_sizes, int n_in,
                              void* d_out, int out_size) {
    (void)in_sizes; (void)n_in; (void)out_size;
    const float* ue = (const float*)d_in[0];
    const float* te = (const float*)d_in[1];
    const float* ge = (const float*)d_in[2];
    const float* W1 = (const float*)d_in[3];
    const float* b1 = (const float*)d_in[4];
    const float* W2 = (const float*)d_in[5];
    const float* b2 = (const float*)d_in[6];
    const float* W3 = (const float*)d_in[7];
    const float* b3 = (const float*)d_in[8];
    float* out = (float*)d_out;

    cudaFuncSetAttribute(pairwise_main,
                         cudaFuncAttributeMaxDynamicSharedMemorySize, SMEM_MAIN);

    prep_kernel<<<394, 128>>>(ue, te, ge, W1, b1, W2);
    pairwise_main<<<304, 256, SMEM_MAIN>>>(b2, W3, b3, out);
}

// round 6
// speedup vs baseline: 1.5922x; 1.1628x over previous
#include <cuda_runtime.h>
#include <cuda_fp16.h>
#include <cstdint>

// ---------------------------------------------------------------------------
// Problem dims
// ---------------------------------------------------------------------------
#define BB 8
#define UU 128
#define TT 256
#define EE 128
#define HH 128
#define NUM_TILES (BB * UU * 2)          // 2048 tiles of 128 t-rows each

// ---------------------------------------------------------------------------
// Device scratch (no allocs allowed)
// ---------------------------------------------------------------------------
__device__ __align__(16) float g_ue_proj[BB * UU * HH];     // ue @ W1u
__device__ __align__(16) float g_te_proj[BB * TT * HH];     // te @ W1t
__device__ __align__(16) float g_gcomb[BB * HH];            // ge @ W1g + b1
__device__ __align__(16) __half g_W2h[HH * HH];             // W2^T fp16 [n][k]
__device__ int g_tile_ctr;

// ---------------------------------------------------------------------------
// PTX helpers (plain sm_103-safe: ldmatrix + mma.sync only)
// ---------------------------------------------------------------------------
__device__ __forceinline__ uint32_t smem_to_u32(const void* p) {
    uint32_t a;
    asm("{ .reg .u64 t; cvta.to.shared.u64 t, %1; cvt.u32.u64 %0, t; }"
        : "=r"(a) : "l"(p));
    return a;
}

__device__ __forceinline__ void ldmatrix_x4(uint32_t& r0, uint32_t& r1,
                                            uint32_t& r2, uint32_t& r3,
                                            uint32_t addr) {
    asm volatile("ldmatrix.sync.aligned.m8n8.x4.shared.b16 {%0,%1,%2,%3}, [%4];"
                 : "=r"(r0), "=r"(r1), "=r"(r2), "=r"(r3) : "r"(addr));
}

__device__ __forceinline__ void mma_fp16(float* c, const uint32_t* a,
                                         const uint32_t* b) {
    asm volatile(
        "mma.sync.aligned.m16n8k16.row.col.f32.f16.f16.f32 "
        "{%0,%1,%2,%3}, {%4,%5,%6,%7}, {%8,%9}, {%0,%1,%2,%3};"
        : "+f"(c[0]), "+f"(c[1]), "+f"(c[2]), "+f"(c[3])
        : "r"(a[0]), "r"(a[1]), "r"(a[2]), "r"(a[3]), "r"(b[0]), "r"(b[1]));
}

// ---------------------------------------------------------------------------
// Math helpers
// ---------------------------------------------------------------------------
__device__ __forceinline__ float gelu_f(float x) {
    return 0.5f * x * (1.0f + erff(x * 0.70710678118654752f));
}

__device__ __forceinline__ uint32_t packh2(float a, float b) {
    __half2 h = __floats2half2_rn(a, b);
    return *reinterpret_cast<uint32_t*>(&h);
}

// ---------------------------------------------------------------------------
// Unified prep kernel, 394 blocks x 128 threads:
//   0..127   : ue rows (8/block)   -> g_ue_proj
//   128..383 : te rows (8/block)   -> g_te_proj
//   384      : ge rows (8) + b1    -> g_gcomb
//   385..392 : W2 fp16 transpose   -> g_W2h ([n][k])
//   393      : tile counter reset
// ---------------------------------------------------------------------------
__global__ __launch_bounds__(128) void prep_kernel(
    const float* __restrict__ ue, const float* __restrict__ te,
    const float* __restrict__ ge, const float* __restrict__ W1,
    const float* __restrict__ b1, const float* __restrict__ W2) {
    __shared__ float s_in[8 * EE];
    const int bid = blockIdx.x;
    const int tid = threadIdx.x;

    if (bid < 385) {
        const float* src;
        float* dst;
        const float* W;
        bool add_b1 = false;
        if (bid < 128) {
            src = ue + bid * 8 * EE;  dst = g_ue_proj + bid * 8 * HH;  W = W1;
        } else if (bid < 384) {
            int r = bid - 128;
            src = te + r * 8 * EE;    dst = g_te_proj + r * 8 * HH;
            W = W1 + EE * HH;
        } else {
            src = ge;  dst = g_gcomb;  W = W1 + 2 * EE * HH;  add_b1 = true;
        }
        for (int i = tid; i < 8 * EE; i += 128) s_in[i] = src[i];
        __syncthreads();

        float acc[8];
        float bb = add_b1 ? b1[tid] : 0.0f;
#pragma unroll
        for (int r = 0; r < 8; r++) acc[r] = bb;
#pragma unroll 4
        for (int e = 0; e < EE; e++) {
            float w = W[e * HH + tid];
#pragma unroll
            for (int r = 0; r < 8; r++)
                acc[r] = fmaf(s_in[r * EE + e], w, acc[r]);
        }
#pragma unroll
        for (int r = 0; r < 8; r++) dst[r * HH + tid] = acc[r];
    } else if (bid < 393) {
        int n0 = (bid - 385) * 16;
        for (int r = 0; r < 16; r++) {
            int n = n0 + r;
            g_W2h[n * HH + tid] = __float2half_rn(W2[tid * HH + n]);
        }
    } else {
        if (tid == 0) g_tile_ctr = 0;
    }
}

// ---------------------------------------------------------------------------
// Main fused kernel (persistent, 8 warps/CTA, 2 CTAs/SM, fp16 HMMA):
//   per tile (b,u,thalf): h1 = gelu(uc + te_proj) -> fp16 A in SMEM
//   -> D = A * W2h (fp32 accum in regs) -> +b2, gelu, dot W3, +b3 -> out
// ---------------------------------------------------------------------------
static constexpr int ST      = 136;                 // row stride in fp16
static constexpr int STB     = ST * 2;              // 272 bytes
static constexpr int TILE_BY = 128 * STB;           // 34816
static constexpr int OFF_A   = 0;
static constexpr int OFF_B   = OFF_A + TILE_BY;
static constexpr int OFF_UC  = OFF_B + TILE_BY;     // 128 floats
static constexpr int OFF_B2S = OFF_UC + 512;        // 128 floats
static constexpr int OFF_W3S = OFF_B2S + 512;       // 128 floats
static constexpr int OFF_PSUM = OFF_W3S + 512;      // 256 floats
static constexpr int OFF_TILE = OFF_PSUM + 1024;
static constexpr int SMEM_MAIN = OFF_TILE + 16;     // ~71.5 KB -> 2 CTAs/SM

__global__ __launch_bounds__(256, 2) void pairwise_main(
    const float* __restrict__ b2, const float* __restrict__ W3,
    const float* __restrict__ b3, float* __restrict__ out) {
    extern __shared__ char smem[];
    const uint32_t smem_base = smem_to_u32(smem);
    const int tid  = threadIdx.x;
    const int wid  = tid >> 5;
    const int lane = tid & 31;

    float* uc   = (float*)(smem + OFF_UC);
    float* b2s  = (float*)(smem + OFF_B2S);
    float* w3s  = (float*)(smem + OFF_W3S);
    float* psum = (float*)(smem + OFF_PSUM);
    int*   stile = (int*)(smem + OFF_TILE);

    // Stage W2 (padded rows) + b2/W3 into SMEM, once.
    {
        const uint4* sb = (const uint4*)g_W2h;
        for (int i = tid; i < 2048; i += 256) {       // 128 rows x 16 uint4
            int r = i >> 4, c = i & 15;
            *(uint4*)(smem + OFF_B + r * STB + c * 16) = sb[i];
        }
        if (tid < 128) { b2s[tid] = b2[tid]; w3s[tid] = W3[tid]; }
    }
    const float bias3 = b3[0];

    // Warp tiling: 4 (M) x 2 (N); each warp owns 32 rows x 64 cols.
    const int mwb   = (wid & 3) * 32;
    const int nh    = wid >> 2;
    const int nbase = nh * 64;

    // h1-stage mapping: 2 threads per row, 64 k-cols each (k-half warp-uniform)
    const int hrow = tid & 127;
    const int hkh  = (tid >> 7) * 64;

    // ldmatrix lane addressing
    const int a_r = mwb + (lane & 15);
    const int a_k = ((lane >> 4) & 1) * 8;
    // B x4: quad 0/1 -> n-tile even (k+0 / k+8); quad 2/3 -> n-tile odd
    const int b_r = nbase + ((lane >> 4) & 1) * 8 + (lane & 7);
    const int b_k = ((lane >> 3) & 1) * 8;

    __syncthreads();

    for (;;) {
        if (tid == 0) stile[0] = atomicAdd(&g_tile_ctr, 1);
        __syncthreads();
        const int tile = stile[0];
        if (tile >= NUM_TILES) break;

        const int b   = tile >> 8;
        const int rem = tile & 255;
        const int u   = rem >> 1;
        const int th  = rem & 1;

        // uc[k] = ue_proj[b,u,k] + (ge@W1g + b1)[b,k]
        if (tid < 128)
            uc[tid] = g_ue_proj[(b * UU + u) * HH + tid] + g_gcomb[b * HH + tid];
        __syncthreads();

        // ---- h1 stage: gelu(te_proj + uc) -> fp16 A tile ----
        {
            const float* terow =
                g_te_proj + ((size_t)(b * TT + th * 128 + hrow)) * HH + hkh;
            const float* ucp = uc + hkh;
            char* arow = smem + OFF_A + hrow * STB + hkh * 2;
#pragma unroll
            for (int c8 = 0; c8 < 64; c8 += 8) {
                float4 t0 = *(const float4*)(terow + c8);
                float4 t1 = *(const float4*)(terow + c8 + 4);
                float4 u0 = *(const float4*)(ucp + c8);
                float4 u1 = *(const float4*)(ucp + c8 + 4);
                float v0 = gelu_f(t0.x + u0.x);
                float v1 = gelu_f(t0.y + u0.y);
                float v2 = gelu_f(t0.z + u0.z);
                float v3 = gelu_f(t0.w + u0.w);
                float v4 = gelu_f(t1.x + u1.x);
                float v5 = gelu_f(t1.y + u1.y);
                float v6 = gelu_f(t1.z + u1.z);
                float v7 = gelu_f(t1.w + u1.w);
                *(uint4*)(arow + c8 * 2) =
                    make_uint4(packh2(v0, v1), packh2(v2, v3),
                               packh2(v4, v5), packh2(v6, v7));
            }
        }
        __syncthreads();

        // ---- GEMM: D = A * W2h (fp32 accum in regs) ----
        float acc[2][8][4];
#pragma unroll
        for (int mt = 0; mt < 2; mt++)
#pragma unroll
            for (int nt = 0; nt < 8; nt++)
#pragma unroll
                for (int i = 0; i < 4; i++) acc[mt][nt][i] = 0.0f;

#pragma unroll
        for (int kt = 0; kt < 8; kt++) {
            const int k0 = kt * 16;
            uint32_t a[2][4];
#pragma unroll
            for (int mt = 0; mt < 2; mt++) {
                uint32_t aaddr =
                    smem_base + OFF_A + (a_r + mt * 16) * STB + (k0 + a_k) * 2;
                ldmatrix_x4(a[mt][0], a[mt][1], a[mt][2], a[mt][3], aaddr);
            }
            uint32_t bh[8][2];
#pragma unroll
            for (int np = 0; np < 4; np++) {          // pairs of n-tiles
                uint32_t baddr =
                    smem_base + OFF_B + (b_r + np * 16) * STB + (k0 + b_k) * 2;
                ldmatrix_x4(bh[np * 2][0], bh[np * 2][1],
                            bh[np * 2 + 1][0], bh[np * 2 + 1][1], baddr);
            }
#pragma unroll
            for (int mt = 0; mt < 2; mt++)
#pragma unroll
                for (int nt = 0; nt < 8; nt++)
                    mma_fp16(acc[mt][nt], a[mt], bh[nt]);
        }

        // ---- Epilogue: gelu(acc + b2) . W3, reduce over N ----
        {
            float b2v[16], w3v[16];
#pragma unroll
            for (int nt = 0; nt < 8; nt++)
#pragma unroll
                for (int j = 0; j < 2; j++) {
                    int col = nbase + nt * 8 + 2 * (lane & 3) + j;
                    b2v[nt * 2 + j] = b2s[col];
                    w3v[nt * 2 + j] = w3s[col];
                }
#pragma unroll
            for (int mt = 0; mt < 2; mt++)
#pragma unroll
                for (int ih = 0; ih < 2; ih++) {
                    float s = 0.0f;
#pragma unroll
                    for (int nt = 0; nt < 8; nt++)
#pragma unroll
                        for (int j = 0; j < 2; j++) {
                            float v = acc[mt][nt][ih * 2 + j];
                            s = fmaf(gelu_f(v + b2v[nt * 2 + j]),
                                     w3v[nt * 2 + j], s);
                        }
                    s += __shfl_xor_sync(0xffffffffu, s, 1);
                    s += __shfl_xor_sync(0xffffffffu, s, 2);
                    if ((lane & 3) == 0) {
                        int row = mwb + mt * 16 + ih * 8 + (lane >> 2);
                        psum[nh * 128 + row] = s;
                    }
                }
        }
        __syncthreads();
        if (tid < 128) {
            out[(size_t)b * (UU * TT) + u * TT + th * 128 + tid] =
                psum[tid] + psum[128 + tid] + bias3;
        }
        __syncthreads();
    }
}

// ---------------------------------------------------------------------------
// Launch
// ---------------------------------------------------------------------------
extern "C" void kernel_launch(void* const* d_in, const int* in_sizes, int n_in,
                              void* d_out, int out_size) {
    (void)in_sizes; (void)n_in; (void)out_size;
    const float* ue = (const float*)d_in[0];
    const float* te = (const float*)d_in[1];
    const float* ge = (const float*)d_in[2];
    const float* W1 = (const float*)d_in[3];
    const float* b1 = (const float*)d_in[4];
    const float* W2 = (const float*)d_in[5];
    const float* b2 = (const float*)d_in[6];
    const float* W3 = (const float*)d_in[7];
    const float* b3 = (const float*)d_in[8];
    float* out = (float*)d_out;

    cudaFuncSetAttribute(pairwise_main,
                         cudaFuncAttributeMaxDynamicSharedMemorySize, SMEM_MAIN);

    prep_kernel<<<394, 128>>>(ue, te, ge, W1, b1, W2);
    pairwise_main<<<304, 256, SMEM_MAIN>>>(b2, W3, b3, out);
}